// round 1
// baseline (speedup 1.0000x reference)
#include <cuda_runtime.h>
#include <cstdint>

// Problem constants (fixed shapes per reference)
constexpr int N_ROWS = 32768;          // 8*4096
constexpr int D      = 512;
constexpr int KSZ    = 4096;

// Output layout (float32), in reference tuple order
constexpr size_t OFF_F    = 0;                               // f_ipmlm [N_ROWS, D]
constexpr size_t OFF_LOSS = (size_t)N_ROWS * D;              // scalar
constexpr size_t OFF_K    = OFF_LOSS + 1;                    // new_K [KSZ, D]
constexpr size_t OFF_ECS  = OFF_K + (size_t)KSZ * D;         // new_ecs [KSZ]
constexpr size_t OFF_EMAW = OFF_ECS + KSZ;                   // new_ema_w [KSZ, D]

// GEMM/argmin tiling
#define TM 128
#define TN 64
#define KC 16
#define SSTRIDE (KC + 2)   // 18 floats: conflict-free smem reads, 8B-aligned pairs

constexpr int ROWTILES = N_ROWS / TM;        // 256
constexpr int CCHUNK   = 512;                // codes per task
constexpr int NCHUNKS  = KSZ / CCHUNK;       // 8
constexpr int NTASKS   = ROWTILES * NCHUNKS; // 2048

// Scratch (device globals; no allocation allowed)
__device__ float               g_y2[KSZ];
__device__ unsigned long long  g_best[N_ROWS];
__device__ float               g_counts[KSZ];
__device__ float               g_dw[(size_t)KSZ * D];
__device__ double              g_loss;
__device__ double              g_n;
__device__ unsigned int        g_task;

// ---------- small helpers ----------
__device__ __forceinline__ void fma2(unsigned long long& c, unsigned long long a,
                                     unsigned long long b) {
    asm("fma.rn.f32x2 %0, %1, %2, %0;" : "+l"(c) : "l"(a), "l"(b));
}

__device__ __forceinline__ float2 unpack2(unsigned long long v) {
    float2 r;
    asm("mov.b64 {%0, %1}, %2;" : "=f"(r.x), "=f"(r.y) : "l"(v));
    return r;
}

__device__ __forceinline__ void cp8(void* s, const float* g) {
    unsigned int sa = (unsigned int)__cvta_generic_to_shared(s);
    asm volatile("cp.async.ca.shared.global [%0], [%1], 8;" :: "r"(sa), "l"(g));
}

// Monotonic float->uint key (handles negatives); smaller float -> smaller key
__device__ __forceinline__ unsigned int fkey(float v) {
    unsigned int b = __float_as_uint(v);
    return (b & 0x80000000u) ? ~b : (b | 0x80000000u);
}

// ---------- kernel 0: zero scratch ----------
__global__ void zero_kernel() {
    int i = blockIdx.x * blockDim.x + threadIdx.x;   // grid covers KSZ*D exactly
    g_dw[i] = 0.0f;
    if (i < KSZ)    g_counts[i] = 0.0f;
    if (i < N_ROWS) g_best[i] = ~0ULL;
    if (i == 0) { g_loss = 0.0; g_n = 0.0; g_task = 0u; }
}

// ---------- kernel 1: code norms ----------
__global__ void y2_kernel(const float* __restrict__ Kc) {
    int k = blockIdx.x;
    const float4* kv = (const float4*)(Kc + (size_t)k * D);
    float4 v = kv[threadIdx.x];
    float s = v.x * v.x + v.y * v.y + v.z * v.z + v.w * v.w;
    #pragma unroll
    for (int o = 16; o > 0; o >>= 1) s += __shfl_down_sync(0xffffffffu, s, o);
    __shared__ float sh[4];
    if ((threadIdx.x & 31) == 0) sh[threadIdx.x >> 5] = s;
    __syncthreads();
    if (threadIdx.x == 0) g_y2[k] = sh[0] + sh[1] + sh[2] + sh[3];
}

// ---------- kernel 2: fused GEMM + argmin (persistent, dynamic tasks) ----------
__global__ __launch_bounds__(256, 2)
void argmin_kernel(const float* __restrict__ f, const float* __restrict__ Kc) {
    __shared__ float As[2][TM][SSTRIDE];
    __shared__ float Bs[2][TN][SSTRIDE];
    __shared__ unsigned long long best[TM];
    __shared__ unsigned int s_task;

    const int tid = threadIdx.x;
    const int jx = tid & 15;   // code lane: codes jx + 16*jj
    const int iy = tid >> 4;   // row lane:  rows  iy + 16*ii

    // loader mapping
    const int ar = tid >> 1;          // As row (0..127)
    const int ak = (tid & 1) * 8;     // As k base
    const int br = tid >> 2;          // Bs row (0..63)
    const int bk = (tid & 3) * 4;     // Bs k base

    while (true) {
        if (tid == 0) s_task = atomicAdd(&g_task, 1u);
        __syncthreads();
        const unsigned int t = s_task;
        if (t >= (unsigned)NTASKS) break;
        const int rows = (int)(t & (ROWTILES - 1)) * TM;
        const int cb   = (int)(t >> 8) * CCHUNK;

        if (tid < TM) best[tid] = ~0ULL;
        __syncthreads();

        for (int ct = cb; ct < cb + CCHUNK; ct += TN) {
            unsigned long long acc[8][4];
            #pragma unroll
            for (int ii = 0; ii < 8; ii++)
                #pragma unroll
                for (int jj = 0; jj < 4; jj++) acc[ii][jj] = 0ULL;

            // prologue: stage 0
            {
                const float* fs = f + (size_t)(rows + ar) * D + ak;
                cp8(&As[0][ar][ak + 0], fs + 0);
                cp8(&As[0][ar][ak + 2], fs + 2);
                cp8(&As[0][ar][ak + 4], fs + 4);
                cp8(&As[0][ar][ak + 6], fs + 6);
                const float* ks = Kc + (size_t)(ct + br) * D + bk;
                cp8(&Bs[0][br][bk + 0], ks + 0);
                cp8(&Bs[0][br][bk + 2], ks + 2);
                asm volatile("cp.async.commit_group;");
            }
            int cur = 0;
            for (int kb = 0; kb < D; kb += KC) {
                if (kb + KC < D) {
                    const int nb = cur ^ 1;
                    const float* fs = f + (size_t)(rows + ar) * D + (kb + KC) + ak;
                    cp8(&As[nb][ar][ak + 0], fs + 0);
                    cp8(&As[nb][ar][ak + 2], fs + 2);
                    cp8(&As[nb][ar][ak + 4], fs + 4);
                    cp8(&As[nb][ar][ak + 6], fs + 6);
                    const float* ks = Kc + (size_t)(ct + br) * D + (kb + KC) + bk;
                    cp8(&Bs[nb][br][bk + 0], ks + 0);
                    cp8(&Bs[nb][br][bk + 2], ks + 2);
                    asm volatile("cp.async.commit_group;");
                    asm volatile("cp.async.wait_group 1;");
                } else {
                    asm volatile("cp.async.wait_group 0;");
                }
                __syncthreads();
                #pragma unroll
                for (int kk = 0; kk < KC; kk += 2) {
                    unsigned long long a[8], b[4];
                    #pragma unroll
                    for (int ii = 0; ii < 8; ii++)
                        a[ii] = *reinterpret_cast<const unsigned long long*>(
                            &As[cur][iy + 16 * ii][kk]);
                    #pragma unroll
                    for (int jj = 0; jj < 4; jj++)
                        b[jj] = *reinterpret_cast<const unsigned long long*>(
                            &Bs[cur][jx + 16 * jj][kk]);
                    #pragma unroll
                    for (int ii = 0; ii < 8; ii++)
                        #pragma unroll
                        for (int jj = 0; jj < 4; jj++)
                            fma2(acc[ii][jj], a[ii], b[jj]);
                }
                __syncthreads();
                cur ^= 1;
            }
            // epilogue: score = ||K||^2 - 2*dot, per-row argmin
            #pragma unroll
            for (int ii = 0; ii < 8; ii++) {
                float bv = 0.0f; int bj = 0;
                #pragma unroll
                for (int jj = 0; jj < 4; jj++) {
                    float2 p = unpack2(acc[ii][jj]);
                    float dot = p.x + p.y;
                    int j = jx + 16 * jj;
                    float sc = __ldg(&g_y2[ct + j]) - 2.0f * dot;
                    if (jj == 0 || sc < bv) { bv = sc; bj = j; }
                }
                unsigned long long pk =
                    ((unsigned long long)fkey(bv) << 32) | (unsigned)(ct + bj);
                atomicMin(&best[iy + 16 * ii], pk);
            }
        }
        __syncthreads();
        if (tid < TM) atomicMin(&g_best[rows + tid], best[tid]);
        __syncthreads();
    }
}

// ---------- kernel 3: gather k1, write f_ipmlm, loss partials, dw/counts scatter ----------
__global__ void gather_kernel(const float* __restrict__ f, const float* __restrict__ Kc,
                              float* __restrict__ out) {
    const int row = blockIdx.x * 2 + (threadIdx.x >> 7);
    const int c4  = threadIdx.x & 127;
    const int idx = (int)(unsigned)(g_best[row] & 0xFFFFFFFFULL);
    float4 kv = __ldg((const float4*)(Kc + (size_t)idx * D) + c4);
    float4 fv = __ldg((const float4*)(f + (size_t)row * D) + c4);
    ((float4*)(out + OFF_F))[(size_t)row * (D / 4) + c4] = kv;
    float dx = kv.x - fv.x, dy = kv.y - fv.y, dz = kv.z - fv.z, dw_ = kv.w - fv.w;
    float s = dx * dx + dy * dy + dz * dz + dw_ * dw_;
    float* dwp = g_dw + (size_t)idx * D + c4 * 4;
    atomicAdd(dwp + 0, fv.x);
    atomicAdd(dwp + 1, fv.y);
    atomicAdd(dwp + 2, fv.z);
    atomicAdd(dwp + 3, fv.w);
    if (c4 == 0) atomicAdd(&g_counts[idx], 1.0f);
    #pragma unroll
    for (int o = 16; o > 0; o >>= 1) s += __shfl_down_sync(0xffffffffu, s, o);
    __shared__ float sh[8];
    if ((threadIdx.x & 31) == 0) sh[threadIdx.x >> 5] = s;
    __syncthreads();
    if (threadIdx.x == 0) {
        float tot = 0.0f;
        #pragma unroll
        for (int w = 0; w < 8; w++) tot += sh[w];
        atomicAdd(&g_loss, (double)tot);
    }
}

// ---------- kernel 4: new_ecs + n ----------
__global__ void ecs_kernel(const float* __restrict__ ecs, float* __restrict__ out) {
    const int i = blockIdx.x * 256 + threadIdx.x;
    float newc = ecs[i] * 0.99f + 0.01f * g_counts[i];
    out[OFF_ECS + i] = newc;
    float s = newc;
    #pragma unroll
    for (int o = 16; o > 0; o >>= 1) s += __shfl_down_sync(0xffffffffu, s, o);
    __shared__ float sh[8];
    if ((threadIdx.x & 31) == 0) sh[threadIdx.x >> 5] = s;
    __syncthreads();
    if (threadIdx.x == 0) {
        float tot = 0.0f;
        #pragma unroll
        for (int w = 0; w < 8; w++) tot += sh[w];
        atomicAdd(&g_n, (double)tot);
    }
}

// ---------- kernel 5: new_ema_w, new_K, loss ----------
__global__ void final_kernel(const float* __restrict__ emaw, float* __restrict__ out) {
    const size_t i = (size_t)blockIdx.x * 256 + threadIdx.x;
    const int k = (int)(i >> 9);   // D = 512
    float neww = emaw[i] * 0.99f + 0.01f * g_dw[i];
    out[OFF_EMAW + i] = neww;
    float nn = (float)g_n;
    float newc = out[OFF_ECS + k];
    float smoothed = (newc + 1e-5f) / (nn + 4096.0f * 1e-5f) * nn;
    out[OFF_K + i] = neww / smoothed;
    if (i == 0)
        out[OFF_LOSS] = (float)(g_loss / ((double)N_ROWS * (double)D));
}

extern "C" void kernel_launch(void* const* d_in, const int* in_sizes, int n_in,
                              void* d_out, int out_size) {
    const float* f    = (const float*)d_in[0];  // [8,4096,512]
    const float* Kc   = (const float*)d_in[1];  // [4096,512]
    const float* ecs  = (const float*)d_in[2];  // [4096]
    const float* emaw = (const float*)d_in[3];  // [4096,512]
    float* out = (float*)d_out;

    zero_kernel<<<(KSZ * D) / 256, 256>>>();
    y2_kernel<<<KSZ, 128>>>(Kc);
    argmin_kernel<<<304, 256>>>(f, Kc);
    gather_kernel<<<N_ROWS / 2, 256>>>(f, Kc, out);
    ecs_kernel<<<KSZ / 256, 256>>>(ecs, out);
    final_kernel<<<(KSZ * D) / 256, 256>>>(emaw, out);
}

// round 3
// speedup vs baseline: 1.6943x; 1.6943x over previous
#include <cuda_runtime.h>
#include <cstdint>

// Problem constants
constexpr int N_ROWS = 32768;          // 8*4096
constexpr int D      = 512;
constexpr int KSZ    = 4096;

// Output layout (float32), reference tuple order
constexpr size_t OFF_F    = 0;
constexpr size_t OFF_LOSS = (size_t)N_ROWS * D;
constexpr size_t OFF_K    = OFF_LOSS + 1;
constexpr size_t OFF_ECS  = OFF_K + (size_t)KSZ * D;
constexpr size_t OFF_EMAW = OFF_ECS + KSZ;

// ---------------- device scratch ----------------
__device__ __align__(16) float g_fhi[(size_t)N_ROWS * D];
__device__ __align__(16) float g_flo[(size_t)N_ROWS * D];
__device__ __align__(16) float g_khi[(size_t)KSZ * D];
__device__ __align__(16) float g_klo[(size_t)KSZ * D];
__device__ float               g_y2[KSZ];
__device__ unsigned long long  g_best[N_ROWS];
__device__ float               g_counts[KSZ];
__device__ float               g_dw[(size_t)KSZ * D];
__device__ double              g_loss;
__device__ double              g_n;

// ---------------- helpers ----------------
__device__ __forceinline__ uint32_t smem_u32(const void* p) {
    uint32_t a;
    asm("{ .reg .u64 t; cvta.to.shared.u64 t, %1; cvt.u32.u64 %0, t; }" : "=r"(a) : "l"(p));
    return a;
}
__device__ __forceinline__ void cp16(uint32_t s, const float* g) {
    asm volatile("cp.async.cg.shared.global [%0], [%1], 16;" :: "r"(s), "l"(g));
}
__device__ __forceinline__ unsigned int fkey(float v) {
    unsigned int b = __float_as_uint(v);
    return (b & 0x80000000u) ? ~b : (b | 0x80000000u);
}
__device__ __forceinline__ float tf32_rna(float x) {
    uint32_t u; asm("cvt.rna.tf32.f32 %0, %1;" : "=r"(u) : "f"(x));
    return __uint_as_float(u);
}
// m16n8k8 tf32 MMA (baseline PTX, runs on tensor pipe as HMMA)
__device__ __forceinline__ void mma8(float* d, const uint32_t* a, const uint32_t* b) {
    asm volatile("mma.sync.aligned.m16n8k8.row.col.f32.tf32.tf32.f32 "
                 "{%0,%1,%2,%3}, {%4,%5,%6,%7}, {%8,%9}, {%0,%1,%2,%3};"
                 : "+f"(d[0]), "+f"(d[1]), "+f"(d[2]), "+f"(d[3])
                 : "r"(a[0]), "r"(a[1]), "r"(a[2]), "r"(a[3]), "r"(b[0]), "r"(b[1]));
}

// ---------------- kernel 0: zero scratch ----------------
__global__ void zero_kernel() {
    int i = blockIdx.x * blockDim.x + threadIdx.x;   // covers KSZ*D
    g_dw[i] = 0.0f;
    if (i < KSZ)    g_counts[i] = 0.0f;
    if (i < N_ROWS) g_best[i] = ~0ULL;
    if (i == 0) { g_loss = 0.0; g_n = 0.0; }
}

// ---------------- kernel 1: tf32 hi/lo split ----------------
__global__ void split_kernel(const float* __restrict__ f, const float* __restrict__ Kc) {
    size_t i = (size_t)blockIdx.x * 256 + threadIdx.x;   // covers N_ROWS*D
    float x = f[i];
    float h = tf32_rna(x);
    g_fhi[i] = h;
    g_flo[i] = tf32_rna(x - h);
    if (i < (size_t)KSZ * D) {
        float y = Kc[i];
        float hy = tf32_rna(y);
        g_khi[i] = hy;
        g_klo[i] = tf32_rna(y - hy);
    }
}

// ---------------- kernel 2: code norms (fp32 exact) ----------------
__global__ void y2_kernel(const float* __restrict__ Kc) {
    int k = blockIdx.x;
    const float4* kv = (const float4*)(Kc + (size_t)k * D);
    float4 v = kv[threadIdx.x];
    float s = v.x * v.x + v.y * v.y + v.z * v.z + v.w * v.w;
    #pragma unroll
    for (int o = 16; o > 0; o >>= 1) s += __shfl_down_sync(0xffffffffu, s, o);
    __shared__ float sh[4];
    if ((threadIdx.x & 31) == 0) sh[threadIdx.x >> 5] = s;
    __syncthreads();
    if (threadIdx.x == 0) g_y2[k] = sh[0] + sh[1] + sh[2] + sh[3];
}

// ---------------- kernel 3: 3xTF32 mma.sync GEMM + argmin epilogue ----------------
// CTA tile 256 rows x 128 codes; 8 warps (2n x 4m) of 64x64; KBLK=16; 3 stages.
constexpr int KBLK   = 16;
constexpr int NKB    = D / KBLK;       // 32
constexpr int STAGES = 3;
constexpr int CODT   = KSZ / 128;      // 32 code tiles (inner for L2 reuse)

// smem stage layout in floats (row stride 20: conflict-free for frag loads)
constexpr int AH_F = 0;                // A hi: 256 x 20
constexpr int AL_F = 5120;             // A lo
constexpr int BH_F = 10240;            // B hi: 128 x 20
constexpr int BL_F = 12800;            // B lo
constexpr int STG_F = 15360;           // floats per stage
constexpr uint32_t STG_B = STG_F * 4;  // 61440 B
constexpr uint32_t SMEM_DYN = STAGES * STG_B;  // 184320 B

__global__ void __launch_bounds__(256, 1)
gemm_kernel() {
    extern __shared__ float smem[];
    __shared__ unsigned long long best[256];
    __shared__ float sy2[128];

    const uint32_t sbase = smem_u32(smem);
    const int tid = threadIdx.x;
    const int wid = tid >> 5;
    const int lane = tid & 31;
    const int g = lane >> 2;        // groupID
    const int c = lane & 3;         // threadInGroup
    const int wm = wid >> 1;        // 0..3 -> warp rows wm*64
    const int wn = wid & 1;         // 0..1 -> warp cols wn*64
    const int wr = wm * 64;
    const int wc = wn * 64;

    const int codetile = blockIdx.x & (CODT - 1);
    const int rowtile  = blockIdx.x >> 5;
    const int row0  = rowtile * 256;
    const int code0 = codetile * 128;

    best[tid] = ~0ULL;
    if (tid < 128) sy2[tid] = g_y2[code0 + tid];

    const float* fa_hi = g_fhi + (size_t)row0 * D;
    const float* fa_lo = g_flo + (size_t)row0 * D;
    const float* kb_hi = g_khi + (size_t)code0 * D;
    const float* kb_lo = g_klo + (size_t)code0 * D;

    // stage fill: 12 cp.async(16B) per thread
    auto fill = [&](int kb) {
        const uint32_t sb = sbase + (uint32_t)(kb % STAGES) * STG_B;
        const int koff = kb * KBLK;
        #pragma unroll
        for (int rep = 0; rep < 4; rep++) {
            const int idx = tid + rep * 256;
            const int r = idx >> 2, kc = idx & 3;
            const uint32_t d = (uint32_t)(r * 80 + kc * 16);
            const size_t gsrc = (size_t)r * D + koff + kc * 4;
            cp16(sb + AH_F * 4 + d, fa_hi + gsrc);
            cp16(sb + AL_F * 4 + d, fa_lo + gsrc);
        }
        #pragma unroll
        for (int rep = 0; rep < 2; rep++) {
            const int idx = tid + rep * 256;
            const int r = idx >> 2, kc = idx & 3;
            const uint32_t d = (uint32_t)(r * 80 + kc * 16);
            const size_t gsrc = (size_t)r * D + koff + kc * 4;
            cp16(sb + BH_F * 4 + d, kb_hi + gsrc);
            cp16(sb + BL_F * 4 + d, kb_lo + gsrc);
        }
        asm volatile("cp.async.commit_group;" ::: "memory");
    };

    fill(0);
    fill(1);

    float acc[4][8][4];
    #pragma unroll
    for (int mt = 0; mt < 4; mt++)
        #pragma unroll
        for (int nt = 0; nt < 8; nt++)
            #pragma unroll
            for (int k = 0; k < 4; k++) acc[mt][nt][k] = 0.0f;

    for (int kb = 0; kb < NKB; kb++) {
        asm volatile("cp.async.wait_group 1;" ::: "memory");
        __syncthreads();
        if (kb + 2 < NKB) fill(kb + 2);
        else asm volatile("cp.async.commit_group;" ::: "memory");

        const float* S = smem + (size_t)(kb % STAGES) * STG_F;
        const float* Sah = S + AH_F;
        const float* Sal = S + AL_F;
        const float* Sbh = S + BH_F;
        const float* Sbl = S + BL_F;

        #pragma unroll
        for (int ks = 0; ks < 2; ks++) {
            const int k0 = ks * 8;
            uint32_t bh[8][2], bl[8][2];
            #pragma unroll
            for (int nt = 0; nt < 8; nt++) {
                const int n = wc + nt * 8 + g;
                bh[nt][0] = __float_as_uint(Sbh[n * 20 + k0 + c]);
                bh[nt][1] = __float_as_uint(Sbh[n * 20 + k0 + 4 + c]);
                bl[nt][0] = __float_as_uint(Sbl[n * 20 + k0 + c]);
                bl[nt][1] = __float_as_uint(Sbl[n * 20 + k0 + 4 + c]);
            }
            #pragma unroll
            for (int mt = 0; mt < 4; mt++) {
                const int r = wr + mt * 16 + g;
                uint32_t ah[4], al[4];
                ah[0] = __float_as_uint(Sah[r * 20 + k0 + c]);
                ah[1] = __float_as_uint(Sah[(r + 8) * 20 + k0 + c]);
                ah[2] = __float_as_uint(Sah[r * 20 + k0 + 4 + c]);
                ah[3] = __float_as_uint(Sah[(r + 8) * 20 + k0 + 4 + c]);
                al[0] = __float_as_uint(Sal[r * 20 + k0 + c]);
                al[1] = __float_as_uint(Sal[(r + 8) * 20 + k0 + c]);
                al[2] = __float_as_uint(Sal[r * 20 + k0 + 4 + c]);
                al[3] = __float_as_uint(Sal[(r + 8) * 20 + k0 + 4 + c]);
                #pragma unroll
                for (int nt = 0; nt < 8; nt++) {
                    mma8(acc[mt][nt], ah, bh[nt]);   // hi*hi
                    mma8(acc[mt][nt], ah, bl[nt]);   // hi*lo
                    mma8(acc[mt][nt], al, bh[nt]);   // lo*hi
                }
            }
        }
        __syncthreads();
    }

    // epilogue: per-row argmin over this CTA's 128 codes
    #pragma unroll
    for (int mt = 0; mt < 4; mt++) {
        #pragma unroll
        for (int half = 0; half < 2; half++) {
            const int r = wr + mt * 16 + g + half * 8;   // local row
            float bv = 3.4e38f; int bj = 0;
            #pragma unroll
            for (int nt = 0; nt < 8; nt++) {
                #pragma unroll
                for (int j = 0; j < 2; j++) {
                    const int col = wc + nt * 8 + c * 2 + j;
                    const float sc = sy2[col] - 2.0f * acc[mt][nt][half * 2 + j];
                    if (sc < bv) { bv = sc; bj = col; }
                }
            }
            const unsigned long long pk =
                ((unsigned long long)fkey(bv) << 32) | (unsigned)(code0 + bj);
            atomicMin(&best[r], pk);
        }
    }
    __syncthreads();
    atomicMin(&g_best[row0 + tid], best[tid]);
}

// ---------------- kernel 4: gather + loss + EMA scatter ----------------
__global__ void gather_kernel(const float* __restrict__ f, const float* __restrict__ Kc,
                              float* __restrict__ out) {
    const int row = blockIdx.x * 2 + (threadIdx.x >> 7);
    const int c4  = threadIdx.x & 127;
    const int idx = (int)(unsigned)(g_best[row] & 0xFFFFFFFFULL);
    float4 kv = __ldg((const float4*)(Kc + (size_t)idx * D) + c4);
    float4 fv = __ldg((const float4*)(f + (size_t)row * D) + c4);
    ((float4*)(out + OFF_F))[(size_t)row * (D / 4) + c4] = kv;
    float dx = kv.x - fv.x, dy = kv.y - fv.y, dz = kv.z - fv.z, dw_ = kv.w - fv.w;
    float s = dx * dx + dy * dy + dz * dz + dw_ * dw_;
    float* dwp = g_dw + (size_t)idx * D + c4 * 4;
    atomicAdd(dwp + 0, fv.x);
    atomicAdd(dwp + 1, fv.y);
    atomicAdd(dwp + 2, fv.z);
    atomicAdd(dwp + 3, fv.w);
    if (c4 == 0) atomicAdd(&g_counts[idx], 1.0f);
    #pragma unroll
    for (int o = 16; o > 0; o >>= 1) s += __shfl_down_sync(0xffffffffu, s, o);
    __shared__ float sh[8];
    if ((threadIdx.x & 31) == 0) sh[threadIdx.x >> 5] = s;
    __syncthreads();
    if (threadIdx.x == 0) {
        float tot = 0.0f;
        #pragma unroll
        for (int w = 0; w < 8; w++) tot += sh[w];
        atomicAdd(&g_loss, (double)tot);
    }
}

// ---------------- kernel 5: new_ecs + n ----------------
__global__ void ecs_kernel(const float* __restrict__ ecs, float* __restrict__ out) {
    const int i = blockIdx.x * 256 + threadIdx.x;
    float newc = ecs[i] * 0.99f + 0.01f * g_counts[i];
    out[OFF_ECS + i] = newc;
    float s = newc;
    #pragma unroll
    for (int o = 16; o > 0; o >>= 1) s += __shfl_down_sync(0xffffffffu, s, o);
    __shared__ float sh[8];
    if ((threadIdx.x & 31) == 0) sh[threadIdx.x >> 5] = s;
    __syncthreads();
    if (threadIdx.x == 0) {
        float tot = 0.0f;
        #pragma unroll
        for (int w = 0; w < 8; w++) tot += sh[w];
        atomicAdd(&g_n, (double)tot);
    }
}

// ---------------- kernel 6: new_ema_w, new_K, loss ----------------
__global__ void final_kernel(const float* __restrict__ emaw, float* __restrict__ out) {
    const size_t i = (size_t)blockIdx.x * 256 + threadIdx.x;
    const int k = (int)(i >> 9);   // D = 512
    float neww = emaw[i] * 0.99f + 0.01f * g_dw[i];
    out[OFF_EMAW + i] = neww;
    float nn = (float)g_n;
    float newc = out[OFF_ECS + k];
    float smoothed = (newc + 1e-5f) / (nn + 4096.0f * 1e-5f) * nn;
    out[OFF_K + i] = neww / smoothed;
    if (i == 0)
        out[OFF_LOSS] = (float)(g_loss / ((double)N_ROWS * (double)D));
}

extern "C" void kernel_launch(void* const* d_in, const int* in_sizes, int n_in,
                              void* d_out, int out_size) {
    const float* f    = (const float*)d_in[0];  // [8,4096,512]
    const float* Kc   = (const float*)d_in[1];  // [4096,512]
    const float* ecs  = (const float*)d_in[2];  // [4096]
    const float* emaw = (const float*)d_in[3];  // [4096,512]
    float* out = (float*)d_out;

    cudaFuncSetAttribute(gemm_kernel, cudaFuncAttributeMaxDynamicSharedMemorySize, SMEM_DYN);

    zero_kernel<<<(KSZ * D) / 256, 256>>>();
    split_kernel<<<(N_ROWS * D) / 256, 256>>>(f, Kc);
    y2_kernel<<<KSZ, 128>>>(Kc);
    gemm_kernel<<<(N_ROWS / 256) * CODT, 256, SMEM_DYN>>>();
    gather_kernel<<<N_ROWS / 2, 256>>>(f, Kc, out);
    ecs_kernel<<<KSZ / 256, 256>>>(ecs, out);
    final_kernel<<<(KSZ * D) / 256, 256>>>(emaw, out);
}

// round 5
// speedup vs baseline: 3.0770x; 1.8161x over previous
#include <cuda_runtime.h>
#include <cuda_fp16.h>
#include <cstdint>

// Problem constants
constexpr int N_ROWS = 32768;          // 8*4096
constexpr int D      = 512;
constexpr int KSZ    = 4096;

// Output layout (float32), reference tuple order
constexpr size_t OFF_F    = 0;
constexpr size_t OFF_LOSS = (size_t)N_ROWS * D;
constexpr size_t OFF_K    = OFF_LOSS + 1;
constexpr size_t OFF_ECS  = OFF_K + (size_t)KSZ * D;
constexpr size_t OFF_EMAW = OFF_ECS + KSZ;

// ---------------- device scratch ----------------
__device__ __align__(16) __half g_fhi[(size_t)N_ROWS * D];
__device__ __align__(16) __half g_flo[(size_t)N_ROWS * D];
__device__ __align__(16) __half g_khi[(size_t)KSZ * D];
__device__ __align__(16) __half g_klo[(size_t)KSZ * D];
__device__ float               g_y2[KSZ];
__device__ unsigned long long  g_best[N_ROWS];
__device__ float               g_counts[KSZ];
__device__ float               g_dw[(size_t)KSZ * D];
__device__ double              g_loss;
__device__ double              g_n;

// ---------------- helpers ----------------
__device__ __forceinline__ uint32_t smem_u32(const void* p) {
    uint32_t a;
    asm("{ .reg .u64 t; cvta.to.shared.u64 t, %1; cvt.u32.u64 %0, t; }" : "=r"(a) : "l"(p));
    return a;
}
__device__ __forceinline__ void cp16(uint32_t s, const void* g) {
    asm volatile("cp.async.cg.shared.global [%0], [%1], 16;" :: "r"(s), "l"(g));
}
__device__ __forceinline__ unsigned int fkey(float v) {
    unsigned int b = __float_as_uint(v);
    return (b & 0x80000000u) ? ~b : (b | 0x80000000u);
}
// m16n8k16 fp16 MMA, fp32 accumulate (baseline PTX, tensor pipe)
__device__ __forceinline__ void mma16(float* d, const uint32_t* a, const uint32_t* b) {
    asm volatile("mma.sync.aligned.m16n8k16.row.col.f32.f16.f16.f32 "
                 "{%0,%1,%2,%3}, {%4,%5,%6,%7}, {%8,%9}, {%0,%1,%2,%3};"
                 : "+f"(d[0]), "+f"(d[1]), "+f"(d[2]), "+f"(d[3])
                 : "r"(a[0]), "r"(a[1]), "r"(a[2]), "r"(a[3]), "r"(b[0]), "r"(b[1]));
}

// ---------------- kernel 0: zero scratch ----------------
__global__ void zero_kernel() {
    int i = blockIdx.x * blockDim.x + threadIdx.x;   // covers KSZ*D
    g_dw[i] = 0.0f;
    if (i < KSZ)    g_counts[i] = 0.0f;
    if (i < N_ROWS) g_best[i] = ~0ULL;
    if (i == 0) { g_loss = 0.0; g_n = 0.0; }
}

// ---------------- kernel 1: fp16 hi/lo split ----------------
__global__ void split_kernel(const float* __restrict__ f, const float* __restrict__ Kc) {
    size_t i = (size_t)blockIdx.x * 256 + threadIdx.x;   // covers N_ROWS*D
    float x = f[i];
    __half h = __float2half_rn(x);
    g_fhi[i] = h;
    g_flo[i] = __float2half_rn(x - __half2float(h));
    if (i < (size_t)KSZ * D) {
        float y = Kc[i];
        __half hy = __float2half_rn(y);
        g_khi[i] = hy;
        g_klo[i] = __float2half_rn(y - __half2float(hy));
    }
}

// ---------------- kernel 2: code norms (fp32 exact) ----------------
__global__ void y2_kernel(const float* __restrict__ Kc) {
    int k = blockIdx.x;
    const float4* kv = (const float4*)(Kc + (size_t)k * D);
    float4 v = kv[threadIdx.x];
    float s = v.x * v.x + v.y * v.y + v.z * v.z + v.w * v.w;
    #pragma unroll
    for (int o = 16; o > 0; o >>= 1) s += __shfl_down_sync(0xffffffffu, s, o);
    __shared__ float sh[4];
    if ((threadIdx.x & 31) == 0) sh[threadIdx.x >> 5] = s;
    __syncthreads();
    if (threadIdx.x == 0) g_y2[k] = sh[0] + sh[1] + sh[2] + sh[3];
}

// ---------------- kernel 3: 3xFP16 mma.sync GEMM + argmin epilogue ----------------
// CTA tile 256 rows x 128 codes; 8 warps (4m x 2n) of 64x64; KBLK=32 halves; 3 stages.
constexpr int KBLK   = 32;             // halves per k-block
constexpr int NKB    = D / KBLK;       // 16
constexpr int STAGES = 3;
constexpr int CODT   = KSZ / 128;      // 32 code tiles (inner for L2 reuse)

// smem stage layout in halves (row stride 40 halves = 20 words: conflict-free)
constexpr int AH_H = 0;                // A hi: 256 x 40
constexpr int AL_H = 10240;            // A lo
constexpr int BH_H = 20480;            // B hi: 128 x 40
constexpr int BL_H = 25600;            // B lo
constexpr int STG_H = 30720;           // halves per stage
constexpr uint32_t STG_B = STG_H * 2;  // 61440 B
constexpr uint32_t SMEM_DYN = STAGES * STG_B;  // 184320 B

__global__ void __launch_bounds__(256, 1)
gemm_kernel() {
    extern __shared__ __half smem[];
    __shared__ unsigned long long best[256];
    __shared__ float sy2[128];

    const uint32_t sbase = smem_u32(smem);
    const int tid = threadIdx.x;
    const int wid = tid >> 5;
    const int lane = tid & 31;
    const int g = lane >> 2;        // groupID
    const int c = lane & 3;         // threadInGroup
    const int wm = wid >> 1;        // 0..3 -> warp rows wm*64
    const int wn = wid & 1;         // 0..1 -> warp cols wn*64
    const int wr = wm * 64;
    const int wc = wn * 64;

    const int codetile = blockIdx.x & (CODT - 1);
    const int rowtile  = blockIdx.x >> 5;
    const int row0  = rowtile * 256;
    const int code0 = codetile * 128;

    best[tid] = ~0ULL;
    if (tid < 128) sy2[tid] = g_y2[code0 + tid];

    const __half* fa_hi = g_fhi + (size_t)row0 * D;
    const __half* fa_lo = g_flo + (size_t)row0 * D;
    const __half* kb_hi = g_khi + (size_t)code0 * D;
    const __half* kb_lo = g_klo + (size_t)code0 * D;

    // stage fill: 12 cp.async(16B) per thread
    auto fill = [&](int kb) {
        const uint32_t sb = sbase + (uint32_t)(kb % STAGES) * STG_B;
        const int koff = kb * KBLK;
        #pragma unroll
        for (int rep = 0; rep < 4; rep++) {           // A: 1024 chunks per split
            const int idx = tid + rep * 256;
            const int r = idx >> 2, kc = idx & 3;
            const uint32_t d = (uint32_t)(r * 80 + kc * 16);
            const size_t gsrc = (size_t)r * D + koff + kc * 8;
            cp16(sb + AH_H * 2 + d, fa_hi + gsrc);
            cp16(sb + AL_H * 2 + d, fa_lo + gsrc);
        }
        #pragma unroll
        for (int rep = 0; rep < 2; rep++) {           // B: 512 chunks per split
            const int idx = tid + rep * 256;
            const int r = idx >> 2, kc = idx & 3;
            const uint32_t d = (uint32_t)(r * 80 + kc * 16);
            const size_t gsrc = (size_t)r * D + koff + kc * 8;
            cp16(sb + BH_H * 2 + d, kb_hi + gsrc);
            cp16(sb + BL_H * 2 + d, kb_lo + gsrc);
        }
        asm volatile("cp.async.commit_group;" ::: "memory");
    };

    fill(0);
    fill(1);

    float acc[4][8][4];
    #pragma unroll
    for (int mt = 0; mt < 4; mt++)
        #pragma unroll
        for (int nt = 0; nt < 8; nt++)
            #pragma unroll
            for (int k = 0; k < 4; k++) acc[mt][nt][k] = 0.0f;

    for (int kb = 0; kb < NKB; kb++) {
        asm volatile("cp.async.wait_group 1;" ::: "memory");
        __syncthreads();
        if (kb + 2 < NKB) fill(kb + 2);
        else asm volatile("cp.async.commit_group;" ::: "memory");

        const __half* S = smem + (size_t)(kb % STAGES) * STG_H;
        const __half* Sah = S + AH_H;
        const __half* Sal = S + AL_H;
        const __half* Sbh = S + BH_H;
        const __half* Sbl = S + BL_H;

        #pragma unroll
        for (int ks = 0; ks < 2; ks++) {
            const int k0 = ks * 16;
            uint32_t bh[8][2], bl[8][2];
            #pragma unroll
            for (int nt = 0; nt < 8; nt++) {
                const int n = wc + nt * 8 + g;
                bh[nt][0] = *(const uint32_t*)&Sbh[n * 40 + k0 + 2 * c];
                bh[nt][1] = *(const uint32_t*)&Sbh[n * 40 + k0 + 2 * c + 8];
                bl[nt][0] = *(const uint32_t*)&Sbl[n * 40 + k0 + 2 * c];
                bl[nt][1] = *(const uint32_t*)&Sbl[n * 40 + k0 + 2 * c + 8];
            }
            #pragma unroll
            for (int mt = 0; mt < 4; mt++) {
                const int r = wr + mt * 16 + g;
                uint32_t ah[4], al[4];
                ah[0] = *(const uint32_t*)&Sah[r * 40 + k0 + 2 * c];
                ah[1] = *(const uint32_t*)&Sah[(r + 8) * 40 + k0 + 2 * c];
                ah[2] = *(const uint32_t*)&Sah[r * 40 + k0 + 2 * c + 8];
                ah[3] = *(const uint32_t*)&Sah[(r + 8) * 40 + k0 + 2 * c + 8];
                al[0] = *(const uint32_t*)&Sal[r * 40 + k0 + 2 * c];
                al[1] = *(const uint32_t*)&Sal[(r + 8) * 40 + k0 + 2 * c];
                al[2] = *(const uint32_t*)&Sal[r * 40 + k0 + 2 * c + 8];
                al[3] = *(const uint32_t*)&Sal[(r + 8) * 40 + k0 + 2 * c + 8];
                #pragma unroll
                for (int nt = 0; nt < 8; nt++) {
                    mma16(acc[mt][nt], ah, bh[nt]);   // hi*hi
                    mma16(acc[mt][nt], ah, bl[nt]);   // hi*lo
                    mma16(acc[mt][nt], al, bh[nt]);   // lo*hi
                }
            }
        }
        __syncthreads();
    }

    // epilogue: per-row argmin over this CTA's 128 codes
    #pragma unroll
    for (int mt = 0; mt < 4; mt++) {
        #pragma unroll
        for (int half = 0; half < 2; half++) {
            const int r = wr + mt * 16 + g + half * 8;   // local row
            float bv = 3.4e38f; int bj = 0;
            #pragma unroll
            for (int nt = 0; nt < 8; nt++) {
                #pragma unroll
                for (int j = 0; j < 2; j++) {
                    const int col = wc + nt * 8 + c * 2 + j;
                    const float sc = sy2[col] - 2.0f * acc[mt][nt][half * 2 + j];
                    if (sc < bv) { bv = sc; bj = col; }
                }
            }
            const unsigned long long pk =
                ((unsigned long long)fkey(bv) << 32) | (unsigned)(code0 + bj);
            atomicMin(&best[r], pk);
        }
    }
    __syncthreads();
    atomicMin(&g_best[row0 + tid], best[tid]);
}

// ---------------- kernel 4: gather + loss + EMA scatter ----------------
__global__ void gather_kernel(const float* __restrict__ f, const float* __restrict__ Kc,
                              float* __restrict__ out) {
    const int row = blockIdx.x * 2 + (threadIdx.x >> 7);
    const int c4  = threadIdx.x & 127;
    const int idx = (int)(unsigned)(g_best[row] & 0xFFFFFFFFULL);
    float4 kv = __ldg((const float4*)(Kc + (size_t)idx * D) + c4);
    float4 fv = __ldg((const float4*)(f + (size_t)row * D) + c4);
    ((float4*)(out + OFF_F))[(size_t)row * (D / 4) + c4] = kv;
    float dx = kv.x - fv.x, dy = kv.y - fv.y, dz = kv.z - fv.z, dw_ = kv.w - fv.w;
    float s = dx * dx + dy * dy + dz * dz + dw_ * dw_;
    float* dwp = g_dw + (size_t)idx * D + c4 * 4;
    atomicAdd(dwp + 0, fv.x);
    atomicAdd(dwp + 1, fv.y);
    atomicAdd(dwp + 2, fv.z);
    atomicAdd(dwp + 3, fv.w);
    if (c4 == 0) atomicAdd(&g_counts[idx], 1.0f);
    #pragma unroll
    for (int o = 16; o > 0; o >>= 1) s += __shfl_down_sync(0xffffffffu, s, o);
    __shared__ float sh[8];
    if ((threadIdx.x & 31) == 0) sh[threadIdx.x >> 5] = s;
    __syncthreads();
    if (threadIdx.x == 0) {
        float tot = 0.0f;
        #pragma unroll
        for (int w = 0; w < 8; w++) tot += sh[w];
        atomicAdd(&g_loss, (double)tot);
    }
}

// ---------------- kernel 5: new_ecs + n ----------------
__global__ void ecs_kernel(const float* __restrict__ ecs, float* __restrict__ out) {
    const int i = blockIdx.x * 256 + threadIdx.x;
    float newc = ecs[i] * 0.99f + 0.01f * g_counts[i];
    out[OFF_ECS + i] = newc;
    float s = newc;
    #pragma unroll
    for (int o = 16; o > 0; o >>= 1) s += __shfl_down_sync(0xffffffffu, s, o);
    __shared__ float sh[8];
    if ((threadIdx.x & 31) == 0) sh[threadIdx.x >> 5] = s;
    __syncthreads();
    if (threadIdx.x == 0) {
        float tot = 0.0f;
        #pragma unroll
        for (int w = 0; w < 8; w++) tot += sh[w];
        atomicAdd(&g_n, (double)tot);
    }
}

// ---------------- kernel 6: new_ema_w, new_K, loss ----------------
__global__ void final_kernel(const float* __restrict__ emaw, float* __restrict__ out) {
    const size_t i = (size_t)blockIdx.x * 256 + threadIdx.x;
    const int k = (int)(i >> 9);   // D = 512
    float neww = emaw[i] * 0.99f + 0.01f * g_dw[i];
    out[OFF_EMAW + i] = neww;
    float nn = (float)g_n;
    float newc = out[OFF_ECS + k];
    float smoothed = (newc + 1e-5f) / (nn + 4096.0f * 1e-5f) * nn;
    out[OFF_K + i] = neww / smoothed;
    if (i == 0)
        out[OFF_LOSS] = (float)(g_loss / ((double)N_ROWS * (double)D));
}

extern "C" void kernel_launch(void* const* d_in, const int* in_sizes, int n_in,
                              void* d_out, int out_size) {
    const float* f    = (const float*)d_in[0];  // [8,4096,512]
    const float* Kc   = (const float*)d_in[1];  // [4096,512]
    const float* ecs  = (const float*)d_in[2];  // [4096]
    const float* emaw = (const float*)d_in[3];  // [4096,512]
    float* out = (float*)d_out;

    cudaFuncSetAttribute(gemm_kernel, cudaFuncAttributeMaxDynamicSharedMemorySize, SMEM_DYN);

    zero_kernel<<<(KSZ * D) / 256, 256>>>();
    split_kernel<<<(N_ROWS * D) / 256, 256>>>(f, Kc);
    y2_kernel<<<KSZ, 128>>>(Kc);
    gemm_kernel<<<(N_ROWS / 256) * CODT, 256, SMEM_DYN>>>();
    gather_kernel<<<N_ROWS / 2, 256>>>(f, Kc, out);
    ecs_kernel<<<KSZ / 256, 256>>>(ecs, out);
    final_kernel<<<(KSZ * D) / 256, 256>>>(emaw, out);
}

// round 7
// speedup vs baseline: 3.0903x; 1.0043x over previous
#include <cuda_runtime.h>
#include <cuda_fp16.h>
#include <cstdint>

// Problem constants
constexpr int N_ROWS = 32768;          // 8*4096
constexpr int D      = 512;
constexpr int KSZ    = 4096;

// Output layout (float32), reference tuple order
constexpr size_t OFF_F    = 0;
constexpr size_t OFF_LOSS = (size_t)N_ROWS * D;
constexpr size_t OFF_K    = OFF_LOSS + 1;
constexpr size_t OFF_ECS  = OFF_K + (size_t)KSZ * D;
constexpr size_t OFF_EMAW = OFF_ECS + KSZ;

// ---------------- device scratch ----------------
__device__ __align__(16) __half g_fhi[(size_t)N_ROWS * D];
__device__ __align__(16) __half g_flo[(size_t)N_ROWS * D];
__device__ __align__(16) __half g_khi[(size_t)KSZ * D];
__device__ __align__(16) __half g_klo[(size_t)KSZ * D];
__device__ float               g_y2[KSZ];
__device__ unsigned long long  g_best[N_ROWS];
__device__ float               g_counts[KSZ];
__device__ float               g_dw[(size_t)KSZ * D];
__device__ double              g_loss;
__device__ double              g_n;

// ---------------- helpers ----------------
__device__ __forceinline__ uint32_t smem_u32(const void* p) {
    uint32_t a;
    asm("{ .reg .u64 t; cvta.to.shared.u64 t, %1; cvt.u32.u64 %0, t; }" : "=r"(a) : "l"(p));
    return a;
}
__device__ __forceinline__ void cp16(uint32_t s, const void* g) {
    asm volatile("cp.async.cg.shared.global [%0], [%1], 16;" :: "r"(s), "l"(g));
}
__device__ __forceinline__ unsigned int fkey(float v) {
    unsigned int b = __float_as_uint(v);
    return (b & 0x80000000u) ? ~b : (b | 0x80000000u);
}
// m16n8k16 fp16 MMA, fp32 accumulate (baseline PTX, tensor pipe)
__device__ __forceinline__ void mma16(float* d, const uint32_t* a, const uint32_t* b) {
    asm volatile("mma.sync.aligned.m16n8k16.row.col.f32.f16.f16.f32 "
                 "{%0,%1,%2,%3}, {%4,%5,%6,%7}, {%8,%9}, {%0,%1,%2,%3};"
                 : "+f"(d[0]), "+f"(d[1]), "+f"(d[2]), "+f"(d[3])
                 : "r"(a[0]), "r"(a[1]), "r"(a[2]), "r"(a[3]), "r"(b[0]), "r"(b[1]));
}

// ---------------- kernel 0: zero scratch ----------------
__global__ void zero_kernel() {
    int i = blockIdx.x * blockDim.x + threadIdx.x;   // covers KSZ*D
    g_dw[i] = 0.0f;
    if (i < KSZ)    g_counts[i] = 0.0f;
    if (i < N_ROWS) g_best[i] = ~0ULL;
    if (i == 0) { g_loss = 0.0; g_n = 0.0; }
}

// ---------------- kernel 1: fp16 hi/lo split ----------------
__global__ void split_kernel(const float* __restrict__ f, const float* __restrict__ Kc) {
    size_t i = (size_t)blockIdx.x * 256 + threadIdx.x;   // covers N_ROWS*D
    float x = f[i];
    __half h = __float2half_rn(x);
    g_fhi[i] = h;
    g_flo[i] = __float2half_rn(x - __half2float(h));
    if (i < (size_t)KSZ * D) {
        float y = Kc[i];
        __half hy = __float2half_rn(y);
        g_khi[i] = hy;
        g_klo[i] = __float2half_rn(y - __half2float(hy));
    }
}

// ---------------- kernel 2: code norms (fp32 exact) ----------------
__global__ void y2_kernel(const float* __restrict__ Kc) {
    int k = blockIdx.x;
    const float4* kv = (const float4*)(Kc + (size_t)k * D);
    float4 v = kv[threadIdx.x];
    float s = v.x * v.x + v.y * v.y + v.z * v.z + v.w * v.w;
    #pragma unroll
    for (int o = 16; o > 0; o >>= 1) s += __shfl_down_sync(0xffffffffu, s, o);
    __shared__ float sh[4];
    if ((threadIdx.x & 31) == 0) sh[threadIdx.x >> 5] = s;
    __syncthreads();
    if (threadIdx.x == 0) g_y2[k] = sh[0] + sh[1] + sh[2] + sh[3];
}

// ---------------- kernel 3: 3xFP16 mma.sync GEMM + argmin epilogue ----------------
// CTA tile 256 rows x 128 codes; 8 warps (4m x 2n) of 64x64; KBLK=32 halves; 3 stages.
constexpr int KBLK   = 32;             // halves per k-block
constexpr int NKB    = D / KBLK;       // 16
constexpr int STAGES = 3;
constexpr int CODT   = KSZ / 128;      // 32 code tiles (inner for L2 reuse)

// smem stage layout in halves (row stride 40 halves = 20 words: conflict-free)
constexpr int AH_H = 0;                // A hi: 256 x 40
constexpr int AL_H = 10240;            // A lo
constexpr int BH_H = 20480;            // B hi: 128 x 40
constexpr int BL_H = 25600;            // B lo
constexpr int STG_H = 30720;           // halves per stage
constexpr uint32_t STG_B = STG_H * 2;  // 61440 B
constexpr uint32_t SMEM_DYN = STAGES * STG_B;  // 184320 B

__global__ void __launch_bounds__(256, 1)
gemm_kernel() {
    extern __shared__ __half smem[];
    __shared__ unsigned long long best[256];
    __shared__ float sy2[128];

    const uint32_t sbase = smem_u32(smem);
    const int tid = threadIdx.x;
    const int wid = tid >> 5;
    const int lane = tid & 31;
    const int g = lane >> 2;        // groupID
    const int c = lane & 3;         // threadInGroup
    const int wm = wid >> 1;        // 0..3 -> warp rows wm*64
    const int wn = wid & 1;         // 0..1 -> warp cols wn*64
    const int wr = wm * 64;
    const int wc = wn * 64;

    const int codetile = blockIdx.x & (CODT - 1);
    const int rowtile  = blockIdx.x >> 5;
    const int row0  = rowtile * 256;
    const int code0 = codetile * 128;

    best[tid] = ~0ULL;
    if (tid < 128) sy2[tid] = g_y2[code0 + tid];

    const __half* fa_hi = g_fhi + (size_t)row0 * D;
    const __half* fa_lo = g_flo + (size_t)row0 * D;
    const __half* kb_hi = g_khi + (size_t)code0 * D;
    const __half* kb_lo = g_klo + (size_t)code0 * D;

    // stage fill: 12 cp.async(16B) per thread
    auto fill = [&](int kb) {
        const uint32_t sb = sbase + (uint32_t)(kb % STAGES) * STG_B;
        const int koff = kb * KBLK;
        #pragma unroll
        for (int rep = 0; rep < 4; rep++) {           // A: 1024 chunks per split
            const int idx = tid + rep * 256;
            const int r = idx >> 2, kc = idx & 3;
            const uint32_t d = (uint32_t)(r * 80 + kc * 16);
            const size_t gsrc = (size_t)r * D + koff + kc * 8;
            cp16(sb + AH_H * 2 + d, fa_hi + gsrc);
            cp16(sb + AL_H * 2 + d, fa_lo + gsrc);
        }
        #pragma unroll
        for (int rep = 0; rep < 2; rep++) {           // B: 512 chunks per split
            const int idx = tid + rep * 256;
            const int r = idx >> 2, kc = idx & 3;
            const uint32_t d = (uint32_t)(r * 80 + kc * 16);
            const size_t gsrc = (size_t)r * D + koff + kc * 8;
            cp16(sb + BH_H * 2 + d, kb_hi + gsrc);
            cp16(sb + BL_H * 2 + d, kb_lo + gsrc);
        }
        asm volatile("cp.async.commit_group;" ::: "memory");
    };

    fill(0);
    fill(1);

    float acc[4][8][4];
    #pragma unroll
    for (int mt = 0; mt < 4; mt++)
        #pragma unroll
        for (int nt = 0; nt < 8; nt++)
            #pragma unroll
            for (int k = 0; k < 4; k++) acc[mt][nt][k] = 0.0f;

    for (int kb = 0; kb < NKB; kb++) {
        asm volatile("cp.async.wait_group 1;" ::: "memory");
        __syncthreads();
        if (kb + 2 < NKB) fill(kb + 2);
        else asm volatile("cp.async.commit_group;" ::: "memory");

        const __half* S = smem + (size_t)(kb % STAGES) * STG_H;
        const __half* Sah = S + AH_H;
        const __half* Sal = S + AL_H;
        const __half* Sbh = S + BH_H;
        const __half* Sbl = S + BL_H;

        #pragma unroll
        for (int ks = 0; ks < 2; ks++) {
            const int k0 = ks * 16;
            // load all fragments for this k-step up front
            uint32_t bh[8][2], bl[8][2];
            #pragma unroll
            for (int nt = 0; nt < 8; nt++) {
                const int n = wc + nt * 8 + g;
                bh[nt][0] = *(const uint32_t*)&Sbh[n * 40 + k0 + 2 * c];
                bh[nt][1] = *(const uint32_t*)&Sbh[n * 40 + k0 + 2 * c + 8];
                bl[nt][0] = *(const uint32_t*)&Sbl[n * 40 + k0 + 2 * c];
                bl[nt][1] = *(const uint32_t*)&Sbl[n * 40 + k0 + 2 * c + 8];
            }
            uint32_t ah[4][4], al[4][4];
            #pragma unroll
            for (int mt = 0; mt < 4; mt++) {
                const int r = wr + mt * 16 + g;
                ah[mt][0] = *(const uint32_t*)&Sah[r * 40 + k0 + 2 * c];
                ah[mt][1] = *(const uint32_t*)&Sah[(r + 8) * 40 + k0 + 2 * c];
                ah[mt][2] = *(const uint32_t*)&Sah[r * 40 + k0 + 2 * c + 8];
                ah[mt][3] = *(const uint32_t*)&Sah[(r + 8) * 40 + k0 + 2 * c + 8];
                al[mt][0] = *(const uint32_t*)&Sal[r * 40 + k0 + 2 * c];
                al[mt][1] = *(const uint32_t*)&Sal[(r + 8) * 40 + k0 + 2 * c];
                al[mt][2] = *(const uint32_t*)&Sal[r * 40 + k0 + 2 * c + 8];
                al[mt][3] = *(const uint32_t*)&Sal[(r + 8) * 40 + k0 + 2 * c + 8];
            }
            // term-major issue: every accumulator re-touched only after 31
            // intervening independent MMAs -> no RAW stalls on the tensor pipe
            #pragma unroll
            for (int mt = 0; mt < 4; mt++)
                #pragma unroll
                for (int nt = 0; nt < 8; nt++)
                    mma16(acc[mt][nt], ah[mt], bh[nt]);   // hi*hi
            #pragma unroll
            for (int mt = 0; mt < 4; mt++)
                #pragma unroll
                for (int nt = 0; nt < 8; nt++)
                    mma16(acc[mt][nt], ah[mt], bl[nt]);   // hi*lo
            #pragma unroll
            for (int mt = 0; mt < 4; mt++)
                #pragma unroll
                for (int nt = 0; nt < 8; nt++)
                    mma16(acc[mt][nt], al[mt], bh[nt]);   // lo*hi
        }
        __syncthreads();
    }

    // epilogue: per-row argmin over this CTA's 128 codes
    #pragma unroll
    for (int mt = 0; mt < 4; mt++) {
        #pragma unroll
        for (int half = 0; half < 2; half++) {
            const int r = wr + mt * 16 + g + half * 8;   // local row
            float bv = 3.4e38f; int bj = 0;
            #pragma unroll
            for (int nt = 0; nt < 8; nt++) {
                #pragma unroll
                for (int j = 0; j < 2; j++) {
                    const int col = wc + nt * 8 + c * 2 + j;
                    const float sc = sy2[col] - 2.0f * acc[mt][nt][half * 2 + j];
                    if (sc < bv) { bv = sc; bj = col; }
                }
            }
            const unsigned long long pk =
                ((unsigned long long)fkey(bv) << 32) | (unsigned)(code0 + bj);
            atomicMin(&best[r], pk);
        }
    }
    __syncthreads();
    atomicMin(&g_best[row0 + tid], best[tid]);
}

// ---------------- kernel 4: gather + loss + EMA scatter ----------------
__global__ void gather_kernel(const float* __restrict__ f, const float* __restrict__ Kc,
                              float* __restrict__ out) {
    const int row = blockIdx.x * 2 + (threadIdx.x >> 7);
    const int c4  = threadIdx.x & 127;
    const int idx = (int)(unsigned)(g_best[row] & 0xFFFFFFFFULL);
    float4 kv = __ldg((const float4*)(Kc + (size_t)idx * D) + c4);
    float4 fv = __ldg((const float4*)(f + (size_t)row * D) + c4);
    ((float4*)(out + OFF_F))[(size_t)row * (D / 4) + c4] = kv;
    float dx = kv.x - fv.x, dy = kv.y - fv.y, dz = kv.z - fv.z, dw_ = kv.w - fv.w;
    float s = dx * dx + dy * dy + dz * dz + dw_ * dw_;
    float* dwp = g_dw + (size_t)idx * D + c4 * 4;
    atomicAdd(dwp + 0, fv.x);
    atomicAdd(dwp + 1, fv.y);
    atomicAdd(dwp + 2, fv.z);
    atomicAdd(dwp + 3, fv.w);
    if (c4 == 0) atomicAdd(&g_counts[idx], 1.0f);
    #pragma unroll
    for (int o = 16; o > 0; o >>= 1) s += __shfl_down_sync(0xffffffffu, s, o);
    __shared__ float sh[8];
    if ((threadIdx.x & 31) == 0) sh[threadIdx.x >> 5] = s;
    __syncthreads();
    if (threadIdx.x == 0) {
        float tot = 0.0f;
        #pragma unroll
        for (int w = 0; w < 8; w++) tot += sh[w];
        atomicAdd(&g_loss, (double)tot);
    }
}

// ---------------- kernel 5: new_ecs + n ----------------
__global__ void ecs_kernel(const float* __restrict__ ecs, float* __restrict__ out) {
    const int i = blockIdx.x * 256 + threadIdx.x;
    float newc = ecs[i] * 0.99f + 0.01f * g_counts[i];
    out[OFF_ECS + i] = newc;
    float s = newc;
    #pragma unroll
    for (int o = 16; o > 0; o >>= 1) s += __shfl_down_sync(0xffffffffu, s, o);
    __shared__ float sh[8];
    if ((threadIdx.x & 31) == 0) sh[threadIdx.x >> 5] = s;
    __syncthreads();
    if (threadIdx.x == 0) {
        float tot = 0.0f;
        #pragma unroll
        for (int w = 0; w < 8; w++) tot += sh[w];
        atomicAdd(&g_n, (double)tot);
    }
}

// ---------------- kernel 6: new_ema_w, new_K, loss ----------------
__global__ void final_kernel(const float* __restrict__ emaw, float* __restrict__ out) {
    const size_t i = (size_t)blockIdx.x * 256 + threadIdx.x;
    const int k = (int)(i >> 9);   // D = 512
    float neww = emaw[i] * 0.99f + 0.01f * g_dw[i];
    out[OFF_EMAW + i] = neww;
    float nn = (float)g_n;
    float newc = out[OFF_ECS + k];
    float smoothed = (newc + 1e-5f) / (nn + 4096.0f * 1e-5f) * nn;
    out[OFF_K + i] = neww / smoothed;
    if (i == 0)
        out[OFF_LOSS] = (float)(g_loss / ((double)N_ROWS * (double)D));
}

extern "C" void kernel_launch(void* const* d_in, const int* in_sizes, int n_in,
                              void* d_out, int out_size) {
    const float* f    = (const float*)d_in[0];  // [8,4096,512]
    const float* Kc   = (const float*)d_in[1];  // [4096,512]
    const float* ecs  = (const float*)d_in[2];  // [4096]
    const float* emaw = (const float*)d_in[3];  // [4096,512]
    float* out = (float*)d_out;

    cudaFuncSetAttribute(gemm_kernel, cudaFuncAttributeMaxDynamicSharedMemorySize, SMEM_DYN);

    zero_kernel<<<(KSZ * D) / 256, 256>>>();
    split_kernel<<<(N_ROWS * D) / 256, 256>>>(f, Kc);
    y2_kernel<<<KSZ, 128>>>(Kc);
    gemm_kernel<<<(N_ROWS / 256) * CODT, 256, SMEM_DYN>>>();
    gather_kernel<<<N_ROWS / 2, 256>>>(f, Kc, out);
    ecs_kernel<<<KSZ / 256, 256>>>(ecs, out);
    final_kernel<<<(KSZ * D) / 256, 256>>>(emaw, out);
}